// round 16
// baseline (speedup 1.0000x reference)
#include <cuda_runtime.h>
#include <cuda_fp16.h>
#include <math.h>
#include <stdint.h>

// Problem dims
constexpr int BB = 32;
constexpr int LL = 256;
constexpr int SS = 64;
constexpr int TT = 64;
constexpr int QD = 768;
constexpr int FD = 1024;
constexpr int HD = 768;
constexpr int OD = 768;
constexpr int TSD = TT * SS;
constexpr int XD = QD + HD;

// Scratch (static device globals).
__device__ __align__(16) __half g_qin_h[(size_t)BB * LL * QD];
__device__ __align__(16) __half g_st_h[2 * (size_t)BB * SS * FD];   // [src|trg]
__device__ __align__(16) __half g_wqT[(size_t)HD * QD];             // [n][k]
__device__ __align__(16) __half g_wstT[2 * (size_t)HD * FD];        // [Ws|Wt] T
__device__ __align__(16) __half g_woT[(size_t)OD * XD];
__device__ __align__(16) __half g_qh[(size_t)BB * LL * HD];
__device__ __align__(16) float  g_stkey[2 * (size_t)BB * SS * HD];  // [skey|tkey]
__device__ __align__(16) __half g_relh[(size_t)BB * TSD * HD];      // [b][ts][h]
__device__ __align__(16) __half g_scoresh[(size_t)BB * LL * TSD];
__device__ __align__(16) __half g_xh[(size_t)BB * LL * XD];

__device__ __forceinline__ void cp16(uint32_t dst_smem, const void* src) {
    asm volatile("cp.async.cg.shared.global [%0], [%1], 16;\n"
                 :: "r"(dst_smem), "l"(src));
}
__device__ __forceinline__ void cp_commit() {
    asm volatile("cp.async.commit_group;\n");
}
template <int N>
__device__ __forceinline__ void cp_wait() {
    asm volatile("cp.async.wait_group %0;\n" :: "n"(N));
}

__device__ __forceinline__ void ldsm4(uint32_t* r, uint32_t addr) {
    asm volatile("ldmatrix.sync.aligned.m8n8.x4.shared.b16 {%0,%1,%2,%3}, [%4];"
                 : "=r"(r[0]), "=r"(r[1]), "=r"(r[2]), "=r"(r[3]) : "r"(addr));
}
__device__ __forceinline__ void ldsm4t(uint32_t* r, uint32_t addr) {
    asm volatile("ldmatrix.sync.aligned.m8n8.x4.trans.shared.b16 {%0,%1,%2,%3}, [%4];"
                 : "=r"(r[0]), "=r"(r[1]), "=r"(r[2]), "=r"(r[3]) : "r"(addr));
}

__device__ __forceinline__ void mma16(float* c, const uint32_t* a,
                                      uint32_t b0, uint32_t b1) {
    asm volatile(
        "mma.sync.aligned.m16n8k16.row.col.f32.f16.f16.f32 "
        "{%0,%1,%2,%3}, {%4,%5,%6,%7}, {%8,%9}, {%0,%1,%2,%3};"
        : "+f"(c[0]), "+f"(c[1]), "+f"(c[2]), "+f"(c[3])
        : "r"(a[0]), "r"(a[1]), "r"(a[2]), "r"(a[3]), "r"(b0), "r"(b1));
}

// ===========================================================================
// Shared GEMM body (EXACT R13 mainloop, proven 596us).
// ===========================================================================
constexpr int NST  = 2;
constexpr int BK   = 64;
constexpr int HSTR = 72;
constexpr int HSTG = 128 * HSTR;
constexpr int BNNSTR = 136;
constexpr int BNNSTG = 64 * BNNSTR;
constexpr int SMEM_BYTES = NST * (HSTG + HSTG) * 2;   // 73728 B

template <bool NT>
__device__ __forceinline__ void hgemm_body(
    __half* smh,
    const __half* __restrict__ Ab, int lda,
    const __half* __restrict__ Bb, int ldb,
    const float* __restrict__ biasz,
    void* __restrict__ Cb, int ldc,
    int K, float scale, int do_relu, int out_half,
    int bm, int bn)
{
    __half* sA = smh;
    __half* sB = smh + NST * HSTG;
    constexpr int BSTG = NT ? HSTG : BNNSTG;

    const int tid  = threadIdx.x;
    const int lane = tid & 31;
    const int wid  = tid >> 5;
    const int wm   = wid & 1;
    const int wn   = wid >> 1;

    const uint32_t aU = (uint32_t)__cvta_generic_to_shared(sA);
    const uint32_t bU = (uint32_t)__cvta_generic_to_shared(sB);

    auto issue = [&](int st, int k0) {
        uint32_t ap = aU + (uint32_t)(st * HSTG * 2);
#pragma unroll
        for (int i = 0; i < 4; i++) {
            int c = tid + 256 * i;
            int r = c >> 3, col = (c & 7) * 8;
            cp16(ap + (r * HSTR + col) * 2, Ab + (size_t)(bm + r) * lda + k0 + col);
        }
        uint32_t bp = bU + (uint32_t)(st * BSTG * 2);
        if (NT) {
#pragma unroll
            for (int i = 0; i < 4; i++) {
                int c = tid + 256 * i;
                int r = c >> 3, col = (c & 7) * 8;
                cp16(bp + (r * HSTR + col) * 2, Bb + (size_t)(bn + r) * ldb + k0 + col);
            }
        } else {
#pragma unroll
            for (int i = 0; i < 4; i++) {
                int c = tid + 256 * i;
                int r = c >> 4, col = (c & 15) * 8;
                cp16(bp + (r * BNNSTR + col) * 2,
                     Bb + (size_t)(k0 + r) * ldb + bn + col);
            }
        }
    };

    float acc[4][4][4] = {};

    auto compute = [&](int st) {
        uint32_t aBase = aU + (uint32_t)(st * HSTG * 2);
        uint32_t bBase = bU + (uint32_t)(st * BSTG * 2);
        const int lrow = lane & 15;
        const int lhalf = lane >> 4;
#pragma unroll
        for (int ks = 0; ks < 4; ks++) {
            const int k0s = ks * 16;
            uint32_t a[4][4];
#pragma unroll
            for (int mt = 0; mt < 4; mt++) {
                int m0 = wm * 64 + mt * 16;
                ldsm4(a[mt], aBase + ((m0 + lrow) * HSTR + k0s + lhalf * 8) * 2);
            }
            uint32_t bf[2][4];
#pragma unroll
            for (int np = 0; np < 2; np++) {
                int n0 = wn * 32 + np * 16;
                if (NT) {
                    ldsm4(bf[np], bBase + ((n0 + lrow) * HSTR + k0s + lhalf * 8) * 2);
                } else {
                    ldsm4t(bf[np], bBase + ((k0s + lrow) * BNNSTR + n0 + lhalf * 8) * 2);
                }
            }
#pragma unroll
            for (int nt = 0; nt < 4; nt++) {
                uint32_t b0, b1;
                if (NT) {
                    b0 = bf[nt >> 1][nt & 1];
                    b1 = bf[nt >> 1][(nt & 1) + 2];
                } else {
                    b0 = bf[nt >> 1][(nt & 1) * 2];
                    b1 = bf[nt >> 1][(nt & 1) * 2 + 1];
                }
#pragma unroll
                for (int mt = 0; mt < 4; mt++)
                    mma16(acc[mt][nt], a[mt], b0, b1);
            }
        }
    };

    const int NI = K / BK;
    issue(0, 0); cp_commit();

    for (int it = 0; it < NI; it++) {
        cp_wait<0>();
        __syncthreads();
        if (it + 1 < NI) {
            issue((it + 1) & 1, (it + 1) * BK);
            cp_commit();
        }
        compute(it & 1);
    }

    // Epilogue
#pragma unroll
    for (int nt = 0; nt < 4; nt++) {
        int col = bn + wn * 32 + nt * 8 + (lane & 3) * 2;
        float bv0 = 0.f, bv1 = 0.f;
        if (biasz) { bv0 = biasz[col]; bv1 = biasz[col + 1]; }
#pragma unroll
        for (int mt = 0; mt < 4; mt++) {
            int r0 = bm + wm * 64 + mt * 16 + (lane >> 2);
            float v0 = acc[mt][nt][0] * scale + bv0;
            float v1 = acc[mt][nt][1] * scale + bv1;
            float v2 = acc[mt][nt][2] * scale + bv0;
            float v3 = acc[mt][nt][3] * scale + bv1;
            if (do_relu) {
                v0 = fmaxf(v0, 0.f); v1 = fmaxf(v1, 0.f);
                v2 = fmaxf(v2, 0.f); v3 = fmaxf(v3, 0.f);
            }
            if (out_half) {
                __half* C = (__half*)Cb;
                __half2 h0 = __floats2half2_rn(v0, v1);
                __half2 h1 = __floats2half2_rn(v2, v3);
                *(__half2*)(C + (size_t)r0 * ldc + col) = h0;
                *(__half2*)(C + (size_t)(r0 + 8) * ldc + col) = h1;
            } else {
                float* C = (float*)Cb;
                *(float2*)(C + (size_t)r0 * ldc + col) = make_float2(v0, v1);
                *(float2*)(C + (size_t)(r0 + 8) * ldc + col) = make_float2(v2, v3);
            }
        }
    }
}

template <bool NT>
__global__ __launch_bounds__(256) void hgemm(
    const __half* __restrict__ A, int lda, size_t sA_,
    const __half* __restrict__ B, int ldb, size_t sB_,
    const float* __restrict__ bias,
    void* __restrict__ Cv, int ldc, size_t sC_,
    int K, float scale, int do_relu, int out_half)
{
    extern __shared__ __half smh[];
    const __half* Ab = A + blockIdx.z * sA_;
    const __half* Bb = B + blockIdx.z * sB_;
    void* Cb = out_half
        ? (void*)((__half*)Cv + blockIdx.z * sC_)
        : (void*)((float*)Cv + blockIdx.z * sC_);
    hgemm_body<NT>(smh, Ab, lda, Bb, ldb, bias, Cb, ldc,
                   K, scale, do_relu, out_half,
                   blockIdx.y * 128, blockIdx.x * 128);
}

// Fused q/s/t projection kernel: grid (6, 64, 3).
__global__ __launch_bounds__(256) void proj_fused_kernel(
    const __half* __restrict__ qin_h, const __half* __restrict__ st_h,
    const __half* __restrict__ wqT, const __half* __restrict__ wstT,
    const float* __restrict__ b_q, const float* __restrict__ b_s,
    const float* __restrict__ b_t,
    __half* __restrict__ qh, float* __restrict__ stkey)
{
    extern __shared__ __half smh[];
    const int z = blockIdx.z;
    if (z > 0 && blockIdx.y >= (BB * SS) / 128) return;
    const __half* Ab;
    const __half* Bb;
    const float* bias;
    void* Cb;
    int lda, K, out_half;
    if (z == 0) {
        Ab = qin_h; lda = QD; Bb = wqT; bias = b_q;
        Cb = qh; K = QD; out_half = 1;
    } else {
        size_t off = (size_t)(z - 1);
        Ab = st_h + off * ((size_t)BB * SS * FD); lda = FD;
        Bb = wstT + off * ((size_t)HD * FD);
        bias = (z == 1) ? b_s : b_t;
        Cb = stkey + off * ((size_t)BB * SS * HD);
        K = FD; out_half = 0;
    }
    hgemm_body<true>(smh, Ab, lda, Bb, lda, bias, Cb, HD,
                     K, 1.f, 0, out_half,
                     blockIdx.y * 128, blockIdx.x * 128);
}

// ---------------------------------------------------------------------------
// Fused prep: fp32 -> half for query, src, trg in ONE launch.
constexpr size_t CVT_C1 = (size_t)BB * LL * QD / 4;
constexpr size_t CVT_C2 = (size_t)BB * SS * FD / 4;
constexpr size_t CVT_TOT = CVT_C1 + 2 * CVT_C2;

__global__ __launch_bounds__(256) void cvt_all_kernel(
    const float* __restrict__ query, const float* __restrict__ src,
    const float* __restrict__ trg,
    __half* __restrict__ qin_h, __half* __restrict__ st_h)
{
    size_t i = (size_t)blockIdx.x * blockDim.x + threadIdx.x;
    const float* sp;
    __half* dp;
    size_t off;
    if (i < CVT_C1)            { sp = query; dp = qin_h; off = i; }
    else if (i < CVT_C1 + CVT_C2) { sp = src; dp = st_h; off = i - CVT_C1; }
    else                       { sp = trg; dp = st_h + (size_t)BB * SS * FD;
                                 off = i - CVT_C1 - CVT_C2; }
    float4 v = ((const float4*)sp)[off];
    __half2 a = __floats2half2_rn(v.x, v.y);
    __half2 b = __floats2half2_rn(v.z, v.w);
    uint2 u;
    u.x = *(uint32_t*)&a; u.y = *(uint32_t*)&b;
    ((uint2*)dp)[off] = u;
}

// Fused transpose+convert for all 4 weights.
__global__ __launch_bounds__(256) void transpose_all_kernel(
    const float* __restrict__ Wq, const float* __restrict__ Ws,
    const float* __restrict__ Wt, const float* __restrict__ Wo,
    __half* __restrict__ wqT, __half* __restrict__ wstT,
    __half* __restrict__ woT)
{
    const int z = blockIdx.z;
    int Kd;
    const float* W;
    __half* WT;
    if (z == 0)      { Kd = QD; W = Wq; WT = wqT; }
    else if (z == 1) { Kd = FD; W = Ws; WT = wstT; }
    else if (z == 2) { Kd = FD; W = Wt; WT = wstT + (size_t)HD * FD; }
    else             { Kd = XD; W = Wo; WT = woT; }
    const int k0 = blockIdx.y * 32;
    if (k0 >= Kd) return;
    const int Nd = HD;
    __shared__ float t[32][33];
    const int tx = threadIdx.x & 31, ty = threadIdx.x >> 5;
    const int n0 = blockIdx.x * 32;
#pragma unroll
    for (int i = 0; i < 4; i++)
        t[ty + 8 * i][tx] = W[(size_t)(k0 + ty + 8 * i) * Nd + n0 + tx];
    __syncthreads();
#pragma unroll
    for (int i = 0; i < 4; i++)
        WT[(size_t)(n0 + ty + 8 * i) * Kd + k0 + tx] = __float2half(t[tx][ty + 8 * i]);
}

// rel = tanh.approx.f16x2(half2(skey + tkey)); 8 halves (16B) per thread.
// Flat grid (R13 version, proven 61us): coalesced, no div in the hot index
// beyond the h8/s/t/b decomposition done once per thread.
__global__ __launch_bounds__(256) void relkey_kernel(
    const float* __restrict__ skey, const float* __restrict__ tkey,
    __half* __restrict__ rel)
{
    const size_t H8 = HD / 8;
    size_t idx = (size_t)blockIdx.x * blockDim.x + threadIdx.x;
    size_t h8 = idx % H8;
    size_t rest = idx / H8;
    int s = (int)(rest % SS); rest /= SS;
    int t = (int)(rest % TT);
    int b = (int)(rest / TT);
    const float4* sp = (const float4*)(skey + ((size_t)b * SS + s) * HD) + h8 * 2;
    const float4* tp = (const float4*)(tkey + ((size_t)b * TT + t) * HD) + h8 * 2;
    float4 sv0 = sp[0], sv1 = sp[1];
    float4 tv0 = tp[0], tv1 = tp[1];
    __half2 x0 = __floats2half2_rn(sv0.x + tv0.x, sv0.y + tv0.y);
    __half2 x1 = __floats2half2_rn(sv0.z + tv0.z, sv0.w + tv0.w);
    __half2 x2 = __floats2half2_rn(sv1.x + tv1.x, sv1.y + tv1.y);
    __half2 x3 = __floats2half2_rn(sv1.z + tv1.z, sv1.w + tv1.w);
    uint4 u;
    asm("tanh.approx.f16x2 %0, %1;" : "=r"(u.x) : "r"(*(uint32_t*)&x0));
    asm("tanh.approx.f16x2 %0, %1;" : "=r"(u.y) : "r"(*(uint32_t*)&x1));
    asm("tanh.approx.f16x2 %0, %1;" : "=r"(u.z) : "r"(*(uint32_t*)&x2));
    asm("tanh.approx.f16x2 %0, %1;" : "=r"(u.w) : "r"(*(uint32_t*)&x3));
    ((uint4*)rel)[idx] = u;
}

// Softmax over 4096 per row: half in/out, in place, vectorized uint4 I/O.
__global__ __launch_bounds__(256) void softmax_kernel(__half* __restrict__ data)
{
    __half* row = data + (size_t)blockIdx.x * TSD;
    const int tid = threadIdx.x;
    uint4 raw[2];
    raw[0] = ((const uint4*)row)[tid];
    raw[1] = ((const uint4*)row)[tid + 256];
    float v[16];
#pragma unroll
    for (int j = 0; j < 2; j++) {
        const uint32_t* w = (const uint32_t*)&raw[j];
#pragma unroll
        for (int k = 0; k < 4; k++) {
            __half2 h = *(const __half2*)&w[k];
            float2 f = __half22float2(h);
            v[j * 8 + k * 2] = f.x;
            v[j * 8 + k * 2 + 1] = f.y;
        }
    }
    float m = -INFINITY;
#pragma unroll
    for (int i = 0; i < 16; i++) m = fmaxf(m, v[i]);
#pragma unroll
    for (int o = 16; o; o >>= 1) m = fmaxf(m, __shfl_xor_sync(0xffffffffu, m, o));
    __shared__ float redm[8];
    __shared__ float reds[8];
    if ((tid & 31) == 0) redm[tid >> 5] = m;
    __syncthreads();
#pragma unroll
    for (int w = 0; w < 8; w++) m = fmaxf(m, redm[w]);
    float s = 0.f;
#pragma unroll
    for (int i = 0; i < 16; i++) {
        v[i] = expf(v[i] - m);
        s += v[i];
    }
#pragma unroll
    for (int o = 16; o; o >>= 1) s += __shfl_xor_sync(0xffffffffu, s, o);
    if ((tid & 31) == 0) reds[tid >> 5] = s;
    __syncthreads();
    s = 0.f;
#pragma unroll
    for (int w = 0; w < 8; w++) s += reds[w];
    float inv = 1.f / s;
#pragma unroll
    for (int j = 0; j < 2; j++) {
        uint32_t* w = (uint32_t*)&raw[j];
#pragma unroll
        for (int k = 0; k < 4; k++) {
            __half2 h = __floats2half2_rn(v[j * 8 + k * 2] * inv,
                                          v[j * 8 + k * 2 + 1] * inv);
            w[k] = *(uint32_t*)&h;
        }
    }
    ((uint4*)row)[tid] = raw[0];
    ((uint4*)row)[tid + 256] = raw[1];
}

// x_h[row][:768] = qin_h[row][:]
__global__ __launch_bounds__(256) void concat_kernel(
    const __half* __restrict__ qh8, __half* __restrict__ x)
{
    const size_t Q8 = QD / 8;
    size_t idx = (size_t)blockIdx.x * blockDim.x + threadIdx.x;
    size_t rowi = idx / Q8;
    size_t c8 = idx % Q8;
    uint4 u = ((const uint4*)qh8)[idx];
    *(uint4*)(x + rowi * XD + c8 * 8) = u;
}

// ---------------------------------------------------------------------------
extern "C" void kernel_launch(void* const* d_in, const int* in_sizes, int n_in,
                              void* d_out, int out_size)
{
    const float* query = (const float*)d_in[0];
    const float* src   = (const float*)d_in[1];
    const float* trg   = (const float*)d_in[2];
    const float* Wq    = (const float*)d_in[3];
    const float* b_q   = (const float*)d_in[4];
    const float* Ws    = (const float*)d_in[5];
    const float* b_s   = (const float*)d_in[6];
    const float* Wt    = (const float*)d_in[7];
    const float* b_t   = (const float*)d_in[8];
    const float* Wo    = (const float*)d_in[9];
    const float* b_o   = (const float*)d_in[10];
    float* out = (float*)d_out;

    __half *qin_h, *st_h, *wqT, *wstT, *woT, *qh, *relh, *scoresh, *xh;
    float *stkey;
    cudaGetSymbolAddress((void**)&qin_h, g_qin_h);
    cudaGetSymbolAddress((void**)&st_h, g_st_h);
    cudaGetSymbolAddress((void**)&wqT, g_wqT);
    cudaGetSymbolAddress((void**)&wstT, g_wstT);
    cudaGetSymbolAddress((void**)&woT, g_woT);
    cudaGetSymbolAddress((void**)&qh, g_qh);
    cudaGetSymbolAddress((void**)&stkey, g_stkey);
    cudaGetSymbolAddress((void**)&relh, g_relh);
    cudaGetSymbolAddress((void**)&scoresh, g_scoresh);
    cudaGetSymbolAddress((void**)&xh, g_xh);

    const float inv_sqrt_h = 1.0f / sqrtf((float)HD);
    dim3 blk(256);

    cudaFuncSetAttribute(hgemm<true>,
                         cudaFuncAttributeMaxDynamicSharedMemorySize, SMEM_BYTES);
    cudaFuncSetAttribute(hgemm<false>,
                         cudaFuncAttributeMaxDynamicSharedMemorySize, SMEM_BYTES);
    cudaFuncSetAttribute(proj_fused_kernel,
                         cudaFuncAttributeMaxDynamicSharedMemorySize, SMEM_BYTES);

    // 0a. fused input conversion
    cvt_all_kernel<<<(unsigned)(CVT_TOT / 256), blk>>>(
        query, src, trg, qin_h, st_h);
    // 0b. fused weight transpose+convert
    transpose_all_kernel<<<dim3(HD / 32, XD / 32, 4), blk>>>(
        Wq, Ws, Wt, Wo, wqT, wstT, woT);

    // 1+2+3. fused projections (q, skey, tkey) in one launch
    proj_fused_kernel<<<dim3(HD / 128, (BB * LL) / 128, 3), blk, SMEM_BYTES>>>(
        qin_h, st_h, wqT, wstT, b_q, b_s, b_t, qh, stkey);

    // 4. rel = tanh.approx(half(skey + tkey))  [flat, R13-proven]
    {
        size_t n8 = (size_t)BB * TSD * HD / 8;
        relkey_kernel<<<(unsigned)(n8 / 256), blk>>>(
            stkey, stkey + (size_t)BB * SS * HD, relh);
    }

    // 5. scores = q . rel^T / sqrt(H)  -> half   [NT]
    hgemm<true><<<dim3(TSD / 128, LL / 128, BB), blk, SMEM_BYTES>>>(
        qh, HD, (size_t)LL * HD,
        relh, HD, (size_t)TSD * HD,
        nullptr,
        scoresh, TSD, (size_t)LL * TSD,
        HD, inv_sqrt_h, 0, 1);

    // 6. softmax in place on half (vectorized I/O)
    softmax_kernel<<<BB * LL, blk>>>(scoresh);

    // 7. x_h[:, :768] = qin_h
    {
        size_t n8 = (size_t)BB * LL * QD / 8;
        concat_kernel<<<(unsigned)(n8 / 256), blk>>>(qin_h, xh);
    }

    // 8. x_h[:, 768:] = scores @ rel  -> half   [NN]
    hgemm<false><<<dim3(HD / 128, LL / 128, BB), blk, SMEM_BYTES>>>(
        scoresh, TSD, (size_t)LL * TSD,
        relh, HD, (size_t)TSD * HD,
        nullptr,
        xh + QD, XD, (size_t)LL * XD,
        TSD, 1.f, 0, 1);

    // 9. out = relu(x @ Wo + b_o) -> fp32
    hgemm<true><<<dim3(OD / 128, (BB * LL) / 128, 1), blk, SMEM_BYTES>>>(
        xh, XD, 0, woT, XD, 0, b_o, out, OD, 0, XD, 1.f, 1, 0);
}

// round 17
// speedup vs baseline: 1.5201x; 1.5201x over previous
#include <cuda_runtime.h>
#include <cuda_fp16.h>
#include <math.h>
#include <stdint.h>

// Problem dims
constexpr int BB = 32;
constexpr int LL = 256;
constexpr int SS = 64;
constexpr int TT = 64;
constexpr int QD = 768;
constexpr int FD = 1024;
constexpr int HD = 768;
constexpr int OD = 768;
constexpr int TSD = TT * SS;
constexpr int XD = QD + HD;

// Scratch (static device globals).
__device__ __align__(16) __half g_qin_h[(size_t)BB * LL * QD];
__device__ __align__(16) __half g_st_h[2 * (size_t)BB * SS * FD];   // [src|trg]
__device__ __align__(16) __half g_wqT[(size_t)HD * QD];             // [n][k]
__device__ __align__(16) __half g_wstT[2 * (size_t)HD * FD];        // [Ws|Wt] T
__device__ __align__(16) __half g_woT[(size_t)OD * XD];
__device__ __align__(16) __half g_qh[(size_t)BB * LL * HD];
__device__ __align__(16) float  g_stkey[2 * (size_t)BB * SS * HD];  // [skey|tkey]
__device__ __align__(16) __half g_relh[(size_t)BB * TSD * HD];      // [b][ts][h]
__device__ __align__(16) __half g_scoresh[(size_t)BB * LL * TSD];
__device__ __align__(16) __half g_xh[(size_t)BB * LL * XD];

__device__ __forceinline__ void cp16(uint32_t dst_smem, const void* src) {
    asm volatile("cp.async.cg.shared.global [%0], [%1], 16;\n"
                 :: "r"(dst_smem), "l"(src));
}
__device__ __forceinline__ void cp_commit() {
    asm volatile("cp.async.commit_group;\n");
}
template <int N>
__device__ __forceinline__ void cp_wait() {
    asm volatile("cp.async.wait_group %0;\n" :: "n"(N));
}

__device__ __forceinline__ void ldsm4(uint32_t* r, uint32_t addr) {
    asm volatile("ldmatrix.sync.aligned.m8n8.x4.shared.b16 {%0,%1,%2,%3}, [%4];"
                 : "=r"(r[0]), "=r"(r[1]), "=r"(r[2]), "=r"(r[3]) : "r"(addr));
}
__device__ __forceinline__ void ldsm4t(uint32_t* r, uint32_t addr) {
    asm volatile("ldmatrix.sync.aligned.m8n8.x4.trans.shared.b16 {%0,%1,%2,%3}, [%4];"
                 : "=r"(r[0]), "=r"(r[1]), "=r"(r[2]), "=r"(r[3]) : "r"(addr));
}

__device__ __forceinline__ void mma16(float* c, const uint32_t* a,
                                      uint32_t b0, uint32_t b1) {
    asm volatile(
        "mma.sync.aligned.m16n8k16.row.col.f32.f16.f16.f32 "
        "{%0,%1,%2,%3}, {%4,%5,%6,%7}, {%8,%9}, {%0,%1,%2,%3};"
        : "+f"(c[0]), "+f"(c[1]), "+f"(c[2]), "+f"(c[3])
        : "r"(a[0]), "r"(a[1]), "r"(a[2]), "r"(a[3]), "r"(b0), "r"(b1));
}

// ===========================================================================
// Shared GEMM body (EXACT R13 mainloop). RE-BENCH ROUND: source identical
// to R15 to measure run-to-run variance (R15 measured 904us on code whose
// components measured 596-598us in R13/R14).
// ===========================================================================
constexpr int NST  = 2;
constexpr int BK   = 64;
constexpr int HSTR = 72;
constexpr int HSTG = 128 * HSTR;
constexpr int BNNSTR = 136;
constexpr int BNNSTG = 64 * BNNSTR;
constexpr int SMEM_BYTES = NST * (HSTG + HSTG) * 2;   // 73728 B

template <bool NT>
__device__ __forceinline__ void hgemm_body(
    __half* smh,
    const __half* __restrict__ Ab, int lda,
    const __half* __restrict__ Bb, int ldb,
    const float* __restrict__ biasz,
    void* __restrict__ Cb, int ldc,
    int K, float scale, int do_relu, int out_half,
    int bm, int bn)
{
    __half* sA = smh;
    __half* sB = smh + NST * HSTG;
    constexpr int BSTG = NT ? HSTG : BNNSTG;

    const int tid  = threadIdx.x;
    const int lane = tid & 31;
    const int wid  = tid >> 5;
    const int wm   = wid & 1;
    const int wn   = wid >> 1;

    const uint32_t aU = (uint32_t)__cvta_generic_to_shared(sA);
    const uint32_t bU = (uint32_t)__cvta_generic_to_shared(sB);

    auto issue = [&](int st, int k0) {
        uint32_t ap = aU + (uint32_t)(st * HSTG * 2);
#pragma unroll
        for (int i = 0; i < 4; i++) {
            int c = tid + 256 * i;
            int r = c >> 3, col = (c & 7) * 8;
            cp16(ap + (r * HSTR + col) * 2, Ab + (size_t)(bm + r) * lda + k0 + col);
        }
        uint32_t bp = bU + (uint32_t)(st * BSTG * 2);
        if (NT) {
#pragma unroll
            for (int i = 0; i < 4; i++) {
                int c = tid + 256 * i;
                int r = c >> 3, col = (c & 7) * 8;
                cp16(bp + (r * HSTR + col) * 2, Bb + (size_t)(bn + r) * ldb + k0 + col);
            }
        } else {
#pragma unroll
            for (int i = 0; i < 4; i++) {
                int c = tid + 256 * i;
                int r = c >> 4, col = (c & 15) * 8;
                cp16(bp + (r * BNNSTR + col) * 2,
                     Bb + (size_t)(k0 + r) * ldb + bn + col);
            }
        }
    };

    float acc[4][4][4] = {};

    auto compute = [&](int st) {
        uint32_t aBase = aU + (uint32_t)(st * HSTG * 2);
        uint32_t bBase = bU + (uint32_t)(st * BSTG * 2);
        const int lrow = lane & 15;
        const int lhalf = lane >> 4;
#pragma unroll
        for (int ks = 0; ks < 4; ks++) {
            const int k0s = ks * 16;
            uint32_t a[4][4];
#pragma unroll
            for (int mt = 0; mt < 4; mt++) {
                int m0 = wm * 64 + mt * 16;
                ldsm4(a[mt], aBase + ((m0 + lrow) * HSTR + k0s + lhalf * 8) * 2);
            }
            uint32_t bf[2][4];
#pragma unroll
            for (int np = 0; np < 2; np++) {
                int n0 = wn * 32 + np * 16;
                if (NT) {
                    ldsm4(bf[np], bBase + ((n0 + lrow) * HSTR + k0s + lhalf * 8) * 2);
                } else {
                    ldsm4t(bf[np], bBase + ((k0s + lrow) * BNNSTR + n0 + lhalf * 8) * 2);
                }
            }
#pragma unroll
            for (int nt = 0; nt < 4; nt++) {
                uint32_t b0, b1;
                if (NT) {
                    b0 = bf[nt >> 1][nt & 1];
                    b1 = bf[nt >> 1][(nt & 1) + 2];
                } else {
                    b0 = bf[nt >> 1][(nt & 1) * 2];
                    b1 = bf[nt >> 1][(nt & 1) * 2 + 1];
                }
#pragma unroll
                for (int mt = 0; mt < 4; mt++)
                    mma16(acc[mt][nt], a[mt], b0, b1);
            }
        }
    };

    const int NI = K / BK;
    issue(0, 0); cp_commit();

    for (int it = 0; it < NI; it++) {
        cp_wait<0>();
        __syncthreads();
        if (it + 1 < NI) {
            issue((it + 1) & 1, (it + 1) * BK);
            cp_commit();
        }
        compute(it & 1);
    }

    // Epilogue
#pragma unroll
    for (int nt = 0; nt < 4; nt++) {
        int col = bn + wn * 32 + nt * 8 + (lane & 3) * 2;
        float bv0 = 0.f, bv1 = 0.f;
        if (biasz) { bv0 = biasz[col]; bv1 = biasz[col + 1]; }
#pragma unroll
        for (int mt = 0; mt < 4; mt++) {
            int r0 = bm + wm * 64 + mt * 16 + (lane >> 2);
            float v0 = acc[mt][nt][0] * scale + bv0;
            float v1 = acc[mt][nt][1] * scale + bv1;
            float v2 = acc[mt][nt][2] * scale + bv0;
            float v3 = acc[mt][nt][3] * scale + bv1;
            if (do_relu) {
                v0 = fmaxf(v0, 0.f); v1 = fmaxf(v1, 0.f);
                v2 = fmaxf(v2, 0.f); v3 = fmaxf(v3, 0.f);
            }
            if (out_half) {
                __half* C = (__half*)Cb;
                __half2 h0 = __floats2half2_rn(v0, v1);
                __half2 h1 = __floats2half2_rn(v2, v3);
                *(__half2*)(C + (size_t)r0 * ldc + col) = h0;
                *(__half2*)(C + (size_t)(r0 + 8) * ldc + col) = h1;
            } else {
                float* C = (float*)Cb;
                *(float2*)(C + (size_t)r0 * ldc + col) = make_float2(v0, v1);
                *(float2*)(C + (size_t)(r0 + 8) * ldc + col) = make_float2(v2, v3);
            }
        }
    }
}

template <bool NT>
__global__ __launch_bounds__(256) void hgemm(
    const __half* __restrict__ A, int lda, size_t sA_,
    const __half* __restrict__ B, int ldb, size_t sB_,
    const float* __restrict__ bias,
    void* __restrict__ Cv, int ldc, size_t sC_,
    int K, float scale, int do_relu, int out_half)
{
    extern __shared__ __half smh[];
    const __half* Ab = A + blockIdx.z * sA_;
    const __half* Bb = B + blockIdx.z * sB_;
    void* Cb = out_half
        ? (void*)((__half*)Cv + blockIdx.z * sC_)
        : (void*)((float*)Cv + blockIdx.z * sC_);
    hgemm_body<NT>(smh, Ab, lda, Bb, ldb, bias, Cb, ldc,
                   K, scale, do_relu, out_half,
                   blockIdx.y * 128, blockIdx.x * 128);
}

// Fused q/s/t projection kernel: grid (6, 64, 3).
__global__ __launch_bounds__(256) void proj_fused_kernel(
    const __half* __restrict__ qin_h, const __half* __restrict__ st_h,
    const __half* __restrict__ wqT, const __half* __restrict__ wstT,
    const float* __restrict__ b_q, const float* __restrict__ b_s,
    const float* __restrict__ b_t,
    __half* __restrict__ qh, float* __restrict__ stkey)
{
    extern __shared__ __half smh[];
    const int z = blockIdx.z;
    if (z > 0 && blockIdx.y >= (BB * SS) / 128) return;
    const __half* Ab;
    const __half* Bb;
    const float* bias;
    void* Cb;
    int lda, K, out_half;
    if (z == 0) {
        Ab = qin_h; lda = QD; Bb = wqT; bias = b_q;
        Cb = qh; K = QD; out_half = 1;
    } else {
        size_t off = (size_t)(z - 1);
        Ab = st_h + off * ((size_t)BB * SS * FD); lda = FD;
        Bb = wstT + off * ((size_t)HD * FD);
        bias = (z == 1) ? b_s : b_t;
        Cb = stkey + off * ((size_t)BB * SS * HD);
        K = FD; out_half = 0;
    }
    hgemm_body<true>(smh, Ab, lda, Bb, lda, bias, Cb, HD,
                     K, 1.f, 0, out_half,
                     blockIdx.y * 128, blockIdx.x * 128);
}

// ---------------------------------------------------------------------------
// Fused prep: fp32 -> half for query, src, trg in ONE launch.
constexpr size_t CVT_C1 = (size_t)BB * LL * QD / 4;
constexpr size_t CVT_C2 = (size_t)BB * SS * FD / 4;
constexpr size_t CVT_TOT = CVT_C1 + 2 * CVT_C2;

__global__ __launch_bounds__(256) void cvt_all_kernel(
    const float* __restrict__ query, const float* __restrict__ src,
    const float* __restrict__ trg,
    __half* __restrict__ qin_h, __half* __restrict__ st_h)
{
    size_t i = (size_t)blockIdx.x * blockDim.x + threadIdx.x;
    const float* sp;
    __half* dp;
    size_t off;
    if (i < CVT_C1)            { sp = query; dp = qin_h; off = i; }
    else if (i < CVT_C1 + CVT_C2) { sp = src; dp = st_h; off = i - CVT_C1; }
    else                       { sp = trg; dp = st_h + (size_t)BB * SS * FD;
                                 off = i - CVT_C1 - CVT_C2; }
    float4 v = ((const float4*)sp)[off];
    __half2 a = __floats2half2_rn(v.x, v.y);
    __half2 b = __floats2half2_rn(v.z, v.w);
    uint2 u;
    u.x = *(uint32_t*)&a; u.y = *(uint32_t*)&b;
    ((uint2*)dp)[off] = u;
}

// Fused transpose+convert for all 4 weights.
__global__ __launch_bounds__(256) void transpose_all_kernel(
    const float* __restrict__ Wq, const float* __restrict__ Ws,
    const float* __restrict__ Wt, const float* __restrict__ Wo,
    __half* __restrict__ wqT, __half* __restrict__ wstT,
    __half* __restrict__ woT)
{
    const int z = blockIdx.z;
    int Kd;
    const float* W;
    __half* WT;
    if (z == 0)      { Kd = QD; W = Wq; WT = wqT; }
    else if (z == 1) { Kd = FD; W = Ws; WT = wstT; }
    else if (z == 2) { Kd = FD; W = Wt; WT = wstT + (size_t)HD * FD; }
    else             { Kd = XD; W = Wo; WT = woT; }
    const int k0 = blockIdx.y * 32;
    if (k0 >= Kd) return;
    const int Nd = HD;
    __shared__ float t[32][33];
    const int tx = threadIdx.x & 31, ty = threadIdx.x >> 5;
    const int n0 = blockIdx.x * 32;
#pragma unroll
    for (int i = 0; i < 4; i++)
        t[ty + 8 * i][tx] = W[(size_t)(k0 + ty + 8 * i) * Nd + n0 + tx];
    __syncthreads();
#pragma unroll
    for (int i = 0; i < 4; i++)
        WT[(size_t)(n0 + ty + 8 * i) * Kd + k0 + tx] = __float2half(t[tx][ty + 8 * i]);
}

// rel = tanh.approx.f16x2(half2(skey + tkey)); 8 halves (16B) per thread.
__global__ __launch_bounds__(256) void relkey_kernel(
    const float* __restrict__ skey, const float* __restrict__ tkey,
    __half* __restrict__ rel)
{
    const size_t H8 = HD / 8;
    size_t idx = (size_t)blockIdx.x * blockDim.x + threadIdx.x;
    size_t h8 = idx % H8;
    size_t rest = idx / H8;
    int s = (int)(rest % SS); rest /= SS;
    int t = (int)(rest % TT);
    int b = (int)(rest / TT);
    const float4* sp = (const float4*)(skey + ((size_t)b * SS + s) * HD) + h8 * 2;
    const float4* tp = (const float4*)(tkey + ((size_t)b * TT + t) * HD) + h8 * 2;
    float4 sv0 = sp[0], sv1 = sp[1];
    float4 tv0 = tp[0], tv1 = tp[1];
    __half2 x0 = __floats2half2_rn(sv0.x + tv0.x, sv0.y + tv0.y);
    __half2 x1 = __floats2half2_rn(sv0.z + tv0.z, sv0.w + tv0.w);
    __half2 x2 = __floats2half2_rn(sv1.x + tv1.x, sv1.y + tv1.y);
    __half2 x3 = __floats2half2_rn(sv1.z + tv1.z, sv1.w + tv1.w);
    uint4 u;
    asm("tanh.approx.f16x2 %0, %1;" : "=r"(u.x) : "r"(*(uint32_t*)&x0));
    asm("tanh.approx.f16x2 %0, %1;" : "=r"(u.y) : "r"(*(uint32_t*)&x1));
    asm("tanh.approx.f16x2 %0, %1;" : "=r"(u.z) : "r"(*(uint32_t*)&x2));
    asm("tanh.approx.f16x2 %0, %1;" : "=r"(u.w) : "r"(*(uint32_t*)&x3));
    ((uint4*)rel)[idx] = u;
}

// Softmax over 4096 per row: half in/out, in place, vectorized uint4 I/O.
__global__ __launch_bounds__(256) void softmax_kernel(__half* __restrict__ data)
{
    __half* row = data + (size_t)blockIdx.x * TSD;
    const int tid = threadIdx.x;
    uint4 raw[2];
    raw[0] = ((const uint4*)row)[tid];
    raw[1] = ((const uint4*)row)[tid + 256];
    float v[16];
#pragma unroll
    for (int j = 0; j < 2; j++) {
        const uint32_t* w = (const uint32_t*)&raw[j];
#pragma unroll
        for (int k = 0; k < 4; k++) {
            __half2 h = *(const __half2*)&w[k];
            float2 f = __half22float2(h);
            v[j * 8 + k * 2] = f.x;
            v[j * 8 + k * 2 + 1] = f.y;
        }
    }
    float m = -INFINITY;
#pragma unroll
    for (int i = 0; i < 16; i++) m = fmaxf(m, v[i]);
#pragma unroll
    for (int o = 16; o; o >>= 1) m = fmaxf(m, __shfl_xor_sync(0xffffffffu, m, o));
    __shared__ float redm[8];
    __shared__ float reds[8];
    if ((tid & 31) == 0) redm[tid >> 5] = m;
    __syncthreads();
#pragma unroll
    for (int w = 0; w < 8; w++) m = fmaxf(m, redm[w]);
    float s = 0.f;
#pragma unroll
    for (int i = 0; i < 16; i++) {
        v[i] = expf(v[i] - m);
        s += v[i];
    }
#pragma unroll
    for (int o = 16; o; o >>= 1) s += __shfl_xor_sync(0xffffffffu, s, o);
    if ((tid & 31) == 0) reds[tid >> 5] = s;
    __syncthreads();
    s = 0.f;
#pragma unroll
    for (int w = 0; w < 8; w++) s += reds[w];
    float inv = 1.f / s;
#pragma unroll
    for (int j = 0; j < 2; j++) {
        uint32_t* w = (uint32_t*)&raw[j];
#pragma unroll
        for (int k = 0; k < 4; k++) {
            __half2 h = __floats2half2_rn(v[j * 8 + k * 2] * inv,
                                          v[j * 8 + k * 2 + 1] * inv);
            w[k] = *(uint32_t*)&h;
        }
    }
    ((uint4*)row)[tid] = raw[0];
    ((uint4*)row)[tid + 256] = raw[1];
}

// x_h[row][:768] = qin_h[row][:]
__global__ __launch_bounds__(256) void concat_kernel(
    const __half* __restrict__ qh8, __half* __restrict__ x)
{
    const size_t Q8 = QD / 8;
    size_t idx = (size_t)blockIdx.x * blockDim.x + threadIdx.x;
    size_t rowi = idx / Q8;
    size_t c8 = idx % Q8;
    uint4 u = ((const uint4*)qh8)[idx];
    *(uint4*)(x + rowi * XD + c8 * 8) = u;
}

// ---------------------------------------------------------------------------
extern "C" void kernel_launch(void* const* d_in, const int* in_sizes, int n_in,
                              void* d_out, int out_size)
{
    const float* query = (const float*)d_in[0];
    const float* src   = (const float*)d_in[1];
    const float* trg   = (const float*)d_in[2];
    const float* Wq    = (const float*)d_in[3];
    const float* b_q   = (const float*)d_in[4];
    const float* Ws    = (const float*)d_in[5];
    const float* b_s   = (const float*)d_in[6];
    const float* Wt    = (const float*)d_in[7];
    const float* b_t   = (const float*)d_in[8];
    const float* Wo    = (const float*)d_in[9];
    const float* b_o   = (const float*)d_in[10];
    float* out = (float*)d_out;

    __half *qin_h, *st_h, *wqT, *wstT, *woT, *qh, *relh, *scoresh, *xh;
    float *stkey;
    cudaGetSymbolAddress((void**)&qin_h, g_qin_h);
    cudaGetSymbolAddress((void**)&st_h, g_st_h);
    cudaGetSymbolAddress((void**)&wqT, g_wqT);
    cudaGetSymbolAddress((void**)&wstT, g_wstT);
    cudaGetSymbolAddress((void**)&woT, g_woT);
    cudaGetSymbolAddress((void**)&qh, g_qh);
    cudaGetSymbolAddress((void**)&stkey, g_stkey);
    cudaGetSymbolAddress((void**)&relh, g_relh);
    cudaGetSymbolAddress((void**)&scoresh, g_scoresh);
    cudaGetSymbolAddress((void**)&xh, g_xh);

    const float inv_sqrt_h = 1.0f / sqrtf((float)HD);
    dim3 blk(256);

    cudaFuncSetAttribute(hgemm<true>,
                         cudaFuncAttributeMaxDynamicSharedMemorySize, SMEM_BYTES);
    cudaFuncSetAttribute(hgemm<false>,
                         cudaFuncAttributeMaxDynamicSharedMemorySize, SMEM_BYTES);
    cudaFuncSetAttribute(proj_fused_kernel,
                         cudaFuncAttributeMaxDynamicSharedMemorySize, SMEM_BYTES);

    // 0a. fused input conversion
    cvt_all_kernel<<<(unsigned)(CVT_TOT / 256), blk>>>(
        query, src, trg, qin_h, st_h);
    // 0b. fused weight transpose+convert
    transpose_all_kernel<<<dim3(HD / 32, XD / 32, 4), blk>>>(
        Wq, Ws, Wt, Wo, wqT, wstT, woT);

    // 1+2+3. fused projections (q, skey, tkey) in one launch
    proj_fused_kernel<<<dim3(HD / 128, (BB * LL) / 128, 3), blk, SMEM_BYTES>>>(
        qin_h, st_h, wqT, wstT, b_q, b_s, b_t, qh, stkey);

    // 4. rel = tanh.approx(half(skey + tkey))
    {
        size_t n8 = (size_t)BB * TSD * HD / 8;
        relkey_kernel<<<(unsigned)(n8 / 256), blk>>>(
            stkey, stkey + (size_t)BB * SS * HD, relh);
    }

    // 5. scores = q . rel^T / sqrt(H)  -> half   [NT]
    hgemm<true><<<dim3(TSD / 128, LL / 128, BB), blk, SMEM_BYTES>>>(
        qh, HD, (size_t)LL * HD,
        relh, HD, (size_t)TSD * HD,
        nullptr,
        scoresh, TSD, (size_t)LL * TSD,
        HD, inv_sqrt_h, 0, 1);

    // 6. softmax in place on half (vectorized I/O)
    softmax_kernel<<<BB * LL, blk>>>(scoresh);

    // 7. x_h[:, :768] = qin_h
    {
        size_t n8 = (size_t)BB * LL * QD / 8;
        concat_kernel<<<(unsigned)(n8 / 256), blk>>>(qin_h, xh);
    }

    // 8. x_h[:, 768:] = scores @ rel  -> half   [NN]
    hgemm<false><<<dim3(HD / 128, LL / 128, BB), blk, SMEM_BYTES>>>(
        scoresh, TSD, (size_t)LL * TSD,
        relh, HD, (size_t)TSD * HD,
        nullptr,
        xh + QD, XD, (size_t)LL * XD,
        TSD, 1.f, 0, 1);

    // 9. out = relu(x @ Wo + b_o) -> fp32
    hgemm<true><<<dim3(OD / 128, (BB * LL) / 128, 1), blk, SMEM_BYTES>>>(
        xh, XD, 0, woT, XD, 0, b_o, out, OD, 0, XD, 1.f, 1, 0);
}